// round 1
// baseline (speedup 1.0000x reference)
#include <cuda_runtime.h>
#include <cstddef>

#define BATCH   8
#define NODES   2048
#define IN_DIM  64
#define HEADS   4
#define OUTD    32
#define DCH     128     // HEADS*OUTD
#define UDIM    1024    // attention only over first 1024 nodes
#define NNB     32      // top-k

// Scratch (no allocs allowed): Q [b][n][c]  8MB, K transposed [b][c][u] 4MB
__device__ float g_Q [BATCH * NODES * DCH];
__device__ float g_Kt[BATCH * DCH * UDIM];

// ---------------------------------------------------------------------------
// Kernel 1: QK projection.
//   Blocks [0,512):  Q rows (8 batches x 64 tiles x 32 rows)
//   Blocks [512,768): K rows (8 batches x 32 tiles x 32 rows), stored transposed
// 128 threads: one output channel per thread; W row held in registers;
// x rows staged in smem (broadcast reads).
// ---------------------------------------------------------------------------
__global__ void __launch_bounds__(128) qk_kernel(
    const float* __restrict__ x,
    const float* __restrict__ Wq, const float* __restrict__ bq,
    const float* __restrict__ Wk, const float* __restrict__ bk)
{
    __shared__ float xs[32][64];
    __shared__ float ks[32][129];   // padded to kill transpose bank conflicts

    const bool isK = (blockIdx.x >= 512);
    int b, row0;
    const float* W; const float* bias;
    if (!isK) { b = blockIdx.x >> 6;            row0 = (blockIdx.x & 63) << 5; W = Wq; bias = bq; }
    else      { int id = blockIdx.x - 512; b = id >> 5; row0 = (id & 31) << 5; W = Wk; bias = bk; }

    const int c = threadIdx.x;

    // stage 32 x-rows
    const float* xb = x + ((size_t)b * NODES + row0) * IN_DIM;
    for (int k = threadIdx.x; k < 32 * 64; k += 128)
        xs[k >> 6][k & 63] = xb[k];

    // W row -> registers
    float4 w[16];
    const float4* Wr = (const float4*)(W + (size_t)c * IN_DIM);
#pragma unroll
    for (int i = 0; i < 16; i++) w[i] = Wr[i];
    const float bb = bias[c];
    __syncthreads();

    if (!isK) {
        float* out = g_Q + ((size_t)b * NODES + row0) * DCH + c;
#pragma unroll 4
        for (int r = 0; r < 32; r++) {
            const float4* xr = (const float4*)xs[r];
            float acc = bb;
#pragma unroll
            for (int i = 0; i < 16; i++) {
                float4 xv = xr[i];
                acc += xv.x * w[i].x + xv.y * w[i].y + xv.z * w[i].z + xv.w * w[i].w;
            }
            out[(size_t)r * DCH] = acc;
        }
    } else {
#pragma unroll 4
        for (int r = 0; r < 32; r++) {
            const float4* xr = (const float4*)xs[r];
            float acc = bb;
#pragma unroll
            for (int i = 0; i < 16; i++) {
                float4 xv = xr[i];
                acc += xv.x * w[i].x + xv.y * w[i].y + xv.z * w[i].z + xv.w * w[i].w;
            }
            ks[r][c] = acc;
        }
        __syncthreads();
        // coalesced transposed store: g_Kt[b][cc][row0+u]
        for (int t = threadIdx.x; t < 32 * 128; t += 128) {
            int cc = t >> 5, u = t & 31;
            g_Kt[((size_t)b * DCH + cc) * UDIM + row0 + u] = ks[u][cc];
        }
    }
}

// ---------------------------------------------------------------------------
// Kernel 2: fused scores + head-mix + top-32 + scatter.
// Block = (batch b, 16 n-rows). 256 threads.
// smem: sc[16][1028] scores, Qt[128][16] (c-major), Ks[128][256] chunk.
// Per-thread tile: 4n x 4u, 4 head accumulators each (64 fp32 accs).
// ---------------------------------------------------------------------------
#define TN   16
#define TUC  256
#define SCS  1028   // padded score row stride (floats)

__global__ void __launch_bounds__(256, 1) agl_main_kernel(
    const float* __restrict__ mlp_w, const float* __restrict__ mlp_b,
    float* __restrict__ out)
{
    extern __shared__ float sm[];
    float* sc = sm;                        // TN * SCS
    float* Qt = sm + TN * SCS;             // DCH * TN
    float* Ks = Qt + DCH * TN;             // DCH * TUC

    const int b  = blockIdx.x >> 7;
    const int n0 = (blockIdx.x & 127) * TN;
    const int tid = threadIdx.x;

    // load Q tile, transposed to c-major
    const float* Qg = g_Q + ((size_t)b * NODES + n0) * DCH;
    for (int k = tid; k < TN * DCH; k += 256) {
        int n = k >> 7, c = k & 127;
        Qt[c * TN + n] = Qg[(size_t)n * DCH + c];
    }

    float m[4][4], mb[4];
#pragma unroll
    for (int o = 0; o < 4; o++) {
        mb[o] = mlp_b[o];
#pragma unroll
        for (int h = 0; h < 4; h++) m[o][h] = mlp_w[o * 4 + h];
    }
    const float inv = 0.17677669529663687f;  // 1/sqrt(32)

    const int tn = (tid & 3) << 2;
    const int tu = (tid >> 2) << 2;

    for (int chk = 0; chk < UDIM / TUC; chk++) {
        const int u0 = chk * TUC;
        __syncthreads();
        // stage K chunk [128c][256u]
        const float* Kg = g_Kt + (size_t)b * DCH * UDIM + u0;
        for (int k = tid; k < DCH * (TUC / 4); k += 256) {
            int c = k >> 6, j4 = k & 63;
            ((float4*)(Ks + c * TUC))[j4] =
                ((const float4*)(Kg + (size_t)c * UDIM))[j4];
        }
        __syncthreads();

        float acc[4][4][4];
#pragma unroll
        for (int h = 0; h < 4; h++)
#pragma unroll
            for (int i = 0; i < 4; i++)
#pragma unroll
                for (int j = 0; j < 4; j++) acc[h][i][j] = 0.f;

#pragma unroll
        for (int h = 0; h < 4; h++) {
#pragma unroll 8
            for (int cc = 0; cc < 32; cc++) {
                const int c = h * 32 + cc;
                const float4 qv = *(const float4*)(Qt + c * TN + tn);
                const float4 kv = *(const float4*)(Ks + c * TUC + tu);
                const float q[4] = {qv.x, qv.y, qv.z, qv.w};
                const float kk[4] = {kv.x, kv.y, kv.z, kv.w};
#pragma unroll
                for (int i = 0; i < 4; i++)
#pragma unroll
                    for (int j = 0; j < 4; j++)
                        acc[h][i][j] += q[i] * kk[j];
            }
        }

        // epilogue: head mix + relu + residual sum -> score
#pragma unroll
        for (int i = 0; i < 4; i++) {
            float4 s4;
#pragma unroll
            for (int j = 0; j < 4; j++) {
                const float a0 = acc[0][i][j] * inv;
                const float a1 = acc[1][i][j] * inv;
                const float a2 = acc[2][i][j] * inv;
                const float a3 = acc[3][i][j] * inv;
                float s = a0 + a1 + a2 + a3;
#pragma unroll
                for (int o = 0; o < 4; o++) {
                    float z = m[o][0] * a0 + m[o][1] * a1 +
                              m[o][2] * a2 + m[o][3] * a3 + mb[o];
                    s += fmaxf(z, 0.f);
                }
                (&s4.x)[j] = s;
            }
            *(float4*)(sc + (tn + i) * SCS + u0 + tu) = s4;
        }
    }
    __syncthreads();

    // ---- top-32 per row (2 rows per warp), jax tie-break = lower index ----
    const int w = tid >> 5, lane = tid & 31;
    for (int rr = 0; rr < 2; rr++) {
        const int row = w * 2 + rr;
        float* srow = sc + row * SCS;
        // cached per-lane local max over its 32 strided elements
        float lb = -3.4e38f; int li = lane;
#pragma unroll
        for (int t = 0; t < 32; t++) {
            float v = srow[t * 32 + lane];
            if (v > lb) { lb = v; li = t * 32 + lane; }  // strict > keeps lowest idx
        }
        float* orow = out + ((size_t)b * NODES + n0 + row) * (size_t)NODES;
        for (int sel = 0; sel < NNB; sel++) {
            float bv = lb; int bi = li;
#pragma unroll
            for (int ms = 16; ms; ms >>= 1) {
                float ov = __shfl_xor_sync(0xffffffffu, bv, ms);
                int   oi = __shfl_xor_sync(0xffffffffu, bi, ms);
                if (ov > bv || (ov == bv && oi < bi)) { bv = ov; bi = oi; }
            }
            if (lane == 0) orow[bi] = bv;
            if ((bi & 31) == lane) {       // owner removes & rescans its slice
                srow[bi] = -3.4e38f;
                lb = -3.4e38f; li = lane;
#pragma unroll
                for (int t = 0; t < 32; t++) {
                    float v = srow[t * 32 + lane];
                    if (v > lb) { lb = v; li = t * 32 + lane; }
                }
            }
        }
    }
}

// ---------------------------------------------------------------------------
extern "C" void kernel_launch(void* const* d_in, const int* in_sizes, int n_in,
                              void* d_out, int out_size)
{
    const float* x     = (const float*)d_in[0];
    const float* Wq    = (const float*)d_in[1];
    const float* bq    = (const float*)d_in[2];
    const float* Wk    = (const float*)d_in[3];
    const float* bk    = (const float*)d_in[4];
    const float* mlp_w = (const float*)d_in[5];
    const float* mlp_b = (const float*)d_in[6];
    // ln_g (d_in[7]) / ln_b (d_in[8]) feed only the deleted adj_static — unused.

    float* out = (float*)d_out;

    // zero the (8,2048,2048) output; scatter fills 32 entries/row afterwards
    cudaMemsetAsync(out, 0, (size_t)out_size * sizeof(float));

    qk_kernel<<<768, 128>>>(x, Wq, bq, Wk, bk);

    const int smem_bytes = (TN * SCS + DCH * TN + DCH * TUC) * (int)sizeof(float);
    cudaFuncSetAttribute(agl_main_kernel,
                         cudaFuncAttributeMaxDynamicSharedMemorySize, smem_bytes);
    agl_main_kernel<<<BATCH * (NODES / TN), 256, smem_bytes>>>(mlp_w, mlp_b, out);
}

// round 3
// speedup vs baseline: 2.6718x; 2.6718x over previous
#include <cuda_runtime.h>
#include <cuda_fp16.h>
#include <cstdint>
#include <cstddef>

#define BATCH   8
#define NODES   2048
#define IN_DIM  64
#define HEADS   4
#define OUTD    32
#define DCH     128
#define UDIM    1024
#define NNB     32

// scratch: pre-split fp16 (hi/lo) operands, packed per head: [h*64 + part*32 + d]
__device__ __half g_Qh[BATCH * NODES * 256];   // [b*2048+n][256]  (Q pre-scaled by 1/sqrt(32))
__device__ __half g_Kh[BATCH * UDIM  * 256];   // [b*1024+u][256]
__device__ float  g_S [BATCH * NODES * UDIM];  // scores

// ---------------------------------------------------------------------------
// Kernel 1: QK projection + fp16 hi/lo split.
//   Blocks [0,512):   Q rows (8b x 64 tiles x 32 rows), scaled by 1/sqrt(32)
//   Blocks [512,768): K rows (8b x 32 tiles x 32 rows), first 1024 nodes only
// ---------------------------------------------------------------------------
__global__ void __launch_bounds__(128) qk_kernel(
    const float* __restrict__ x,
    const float* __restrict__ Wq, const float* __restrict__ bq,
    const float* __restrict__ Wk, const float* __restrict__ bk)
{
    __shared__ float xs[32][64];

    const bool isK = (blockIdx.x >= 512);
    int b, row0;
    const float* W; const float* bias;
    if (!isK) { b = blockIdx.x >> 6;            row0 = (blockIdx.x & 63) << 5; W = Wq; bias = bq; }
    else      { int id = blockIdx.x - 512; b = id >> 5; row0 = (id & 31) << 5; W = Wk; bias = bk; }

    const int c = threadIdx.x;
    const float* xb = x + ((size_t)b * NODES + row0) * IN_DIM;
    for (int k = threadIdx.x; k < 32 * 64; k += 128)
        xs[k >> 6][k & 63] = xb[k];

    float4 w[16];
    const float4* Wr = (const float4*)(W + (size_t)c * IN_DIM);
#pragma unroll
    for (int i = 0; i < 16; i++) w[i] = Wr[i];
    const float bb = bias[c];
    __syncthreads();

    const float scale = isK ? 1.0f : 0.17677669529663687f;   // 1/sqrt(32) folded into Q
    const int col = ((c >> 5) << 6) + (c & 31);              // h*64 + d
    __half* dst = (isK ? g_Kh : g_Qh) +
                  ((size_t)b * (isK ? UDIM : NODES) + row0) * 256;

#pragma unroll 4
    for (int r = 0; r < 32; r++) {
        const float4* xr = (const float4*)xs[r];
        float acc = bb;
#pragma unroll
        for (int i = 0; i < 16; i++) {
            float4 xv = xr[i];
            acc += xv.x * w[i].x + xv.y * w[i].y + xv.z * w[i].z + xv.w * w[i].w;
        }
        acc *= scale;
        __half hh = __float2half_rn(acc);
        float  lo = acc - __half2float(hh);
        __half hl = __float2half_rn(lo);
        dst[(size_t)r * 256 + col]      = hh;
        dst[(size_t)r * 256 + col + 32] = hl;
    }
}

// ---------------------------------------------------------------------------
// Kernel 2: HMMA score kernel.
// Block = (b, 128 n-rows), 256 threads (8 warps), warp tile 16n x 32u.
// u-chunks of 32, 32 iterations, K double-buffered in smem.
// Exact-style split: acc = sum over (pa,pb) in {h,l}^2 of Q_pa * K_pb.
// ---------------------------------------------------------------------------
#define KROW   528                    // 256 halfs (512B) + 16B pad per row
#define KSZ    (32 * KROW)            // one K buffer: 16896 B
#define SQOFF  (2 * KSZ)              // Q region at 33792
#define SMEMSZ (SQOFF + 128 * KROW)   // 101376 B

__device__ __forceinline__ void mma_f16(float* c, const uint32_t* a, const uint32_t* b) {
    asm volatile("mma.sync.aligned.m16n8k16.row.col.f32.f16.f16.f32 "
        "{%0,%1,%2,%3}, {%4,%5,%6,%7}, {%8,%9}, {%0,%1,%2,%3};"
        : "+f"(c[0]), "+f"(c[1]), "+f"(c[2]), "+f"(c[3])
        : "r"(a[0]), "r"(a[1]), "r"(a[2]), "r"(a[3]), "r"(b[0]), "r"(b[1]));
}

__device__ __forceinline__ void fill_K(char* sm, int b, int chunk, int buf, int tid) {
    const uint4* src = (const uint4*)(g_Kh + ((size_t)b * UDIM + chunk * 32) * 256);
#pragma unroll
    for (int it = 0; it < 4; it++) {
        int idx = it * 256 + tid;          // 1024 x 16B
        int row = idx >> 5, j = idx & 31;
        *(uint4*)(sm + buf * KSZ + row * KROW + j * 16) = src[row * 32 + j];
    }
}

__global__ void __launch_bounds__(256, 1) score_kernel(
    const float* __restrict__ mlp_w, const float* __restrict__ mlp_b)
{
    extern __shared__ __align__(16) char sm[];
    const int tid = threadIdx.x, lane = tid & 31;
    const int wr0 = (tid >> 5) << 4;           // warp's first n-row (0..112)
    const int b  = blockIdx.x >> 4;
    const int n0 = (blockIdx.x & 15) << 7;

    // ---- stage Q tile (128 rows x 512B) ----
    {
        const uint4* src = (const uint4*)(g_Qh + ((size_t)b * NODES + n0) * 256);
        for (int idx = tid; idx < 128 * 32; idx += 256) {
            int row = idx >> 5, j = idx & 31;
            *(uint4*)(sm + SQOFF + row * KROW + j * 16) = src[row * 32 + j];
        }
    }
    fill_K(sm, b, 0, 0, tid);

    float mm[4][4], mb_[4];
#pragma unroll
    for (int o = 0; o < 4; o++) {
        mb_[o] = mlp_b[o];
#pragma unroll
        for (int h = 0; h < 4; h++) mm[o][h] = mlp_w[o * 4 + h];
    }
    __syncthreads();

    // ---- A fragments -> registers (reused for all 32 chunks) ----
    uint32_t aF[4][2][2][4];                   // [head][part][kstep][frag]
    {
        const char* qb = sm + SQOFF + (wr0 + (lane >> 2)) * KROW;
#pragma unroll
        for (int h = 0; h < 4; h++)
#pragma unroll
            for (int p = 0; p < 2; p++)
#pragma unroll
                for (int s = 0; s < 2; s++) {
                    int off = (h * 64 + p * 32 + s * 16 + (lane & 3) * 2) * 2;
                    aF[h][p][s][0] = *(const uint32_t*)(qb + off);
                    aF[h][p][s][1] = *(const uint32_t*)(qb + off + 8 * KROW);
                    aF[h][p][s][2] = *(const uint32_t*)(qb + off + 16);
                    aF[h][p][s][3] = *(const uint32_t*)(qb + off + 8 * KROW + 16);
                }
    }
    __syncthreads();

    for (int ck = 0; ck < 32; ck++) {
        const int buf = ck & 1;
        if (ck + 1 < 32) fill_K(sm, b, ck + 1, buf ^ 1, tid);

        float acc[4][4][4];                    // [utile][head][frag]
#pragma unroll
        for (int ut = 0; ut < 4; ut++)
#pragma unroll
            for (int h = 0; h < 4; h++)
#pragma unroll
                for (int j = 0; j < 4; j++) acc[ut][h][j] = 0.f;

#pragma unroll
        for (int ut = 0; ut < 4; ut++) {
            const char* kb = sm + buf * KSZ + (ut * 8 + (lane >> 2)) * KROW;
#pragma unroll
            for (int h = 0; h < 4; h++) {
                uint32_t bb[2][2][2];          // [part][kstep][frag]
#pragma unroll
                for (int p = 0; p < 2; p++)
#pragma unroll
                    for (int s = 0; s < 2; s++) {
                        int off = (h * 64 + p * 32 + s * 16 + (lane & 3) * 2) * 2;
                        bb[p][s][0] = *(const uint32_t*)(kb + off);
                        bb[p][s][1] = *(const uint32_t*)(kb + off + 16);
                    }
#pragma unroll
                for (int pa = 0; pa < 2; pa++)
#pragma unroll
                    for (int pb = 0; pb < 2; pb++)
#pragma unroll
                        for (int s = 0; s < 2; s++)
                            mma_f16(acc[ut][h], aF[h][pa][s], bb[pb][s]);
            }
        }

        // epilogue: head mix + relu + residual, straight to gmem
        const int u0 = ck * 32;
#pragma unroll
        for (int ut = 0; ut < 4; ut++) {
            float s_[4];
#pragma unroll
            for (int j = 0; j < 4; j++) {
                float a0 = acc[ut][0][j], a1 = acc[ut][1][j];
                float a2 = acc[ut][2][j], a3 = acc[ut][3][j];
                float s = a0 + a1 + a2 + a3;
#pragma unroll
                for (int o = 0; o < 4; o++) {
                    float z = fmaf(mm[o][0], a0, fmaf(mm[o][1], a1,
                              fmaf(mm[o][2], a2, fmaf(mm[o][3], a3, mb_[o]))));
                    s += fmaxf(z, 0.f);
                }
                s_[j] = s;
            }
            float* base = g_S + ((size_t)(b * NODES + n0 + wr0 + (lane >> 2)) * UDIM
                                 + u0 + ut * 8 + (lane & 3) * 2);
            *(float2*)base                = make_float2(s_[0], s_[1]);
            *(float2*)(base + 8 * UDIM)   = make_float2(s_[2], s_[3]);
        }
        __syncthreads();
    }
}

// ---------------------------------------------------------------------------
// Kernel 3: top-32 per row via 4-level 8-bit radix select (exact, jax ties).
// 1 warp per row; warp also zero-fills its 2048-wide output row.
// ---------------------------------------------------------------------------
__global__ void __launch_bounds__(256) topk_kernel(float* __restrict__ out)
{
    const int w = threadIdx.x >> 5, lane = threadIdx.x & 31;
    const int row = blockIdx.x * 8 + w;
    __shared__ unsigned hist[8][256];
    __shared__ unsigned tie_idx[8][64];
    __shared__ unsigned found[8][2];
    __shared__ unsigned tie_cnt[8];

    const float* srow = g_S + (size_t)row * UDIM;
    float    vals[32];
    unsigned keys[32];
#pragma unroll
    for (int j = 0; j < 32; j++) {
        float v = srow[j * 32 + lane];
        vals[j] = v;
        unsigned u = __float_as_uint(v);
        keys[j] = u ^ (((unsigned)((int)u >> 31)) | 0x80000000u);
    }

    // zero-fill output row (replaces global memset; d_out arrives poisoned)
    const int b = row >> 11, n = row & 2047;
    float* orow = out + ((size_t)b * NODES + n) * (size_t)NODES;
    const float4 z4 = make_float4(0.f, 0.f, 0.f, 0.f);
#pragma unroll
    for (int t = lane; t < NODES / 4; t += 32) ((float4*)orow)[t] = z4;

    unsigned prefix = 0;
    int needed = NNB;
    for (int shift = 24; shift >= 0; shift -= 8) {
        for (int t = lane; t < 256; t += 32) hist[w][t] = 0;
        __syncwarp();
        const unsigned hm = (shift == 24) ? 0u : (0xFFFFFFFFu << (shift + 8));
#pragma unroll
        for (int j = 0; j < 32; j++)
            if (((keys[j] ^ prefix) & hm) == 0)
                atomicAdd(&hist[w][(keys[j] >> shift) & 255], 1u);
        __syncwarp();
        unsigned s = 0;
#pragma unroll
        for (int t = 0; t < 8; t++) s += hist[w][lane * 8 + t];
        unsigned rs = s;
#pragma unroll
        for (int off = 1; off < 32; off <<= 1) {
            unsigned v = __shfl_down_sync(0xffffffffu, rs, off);
            if (lane + off < 32) rs += v;
        }
        unsigned acc = rs - s;            // keys in strictly-higher buckets
        for (int t = 7; t >= 0; t--) {
            unsigned c = hist[w][lane * 8 + t];
            if ((int)acc < needed && needed <= (int)(acc + c)) {
                found[w][0] = (unsigned)(lane * 8 + t);
                found[w][1] = acc;
            }
            acc += c;
        }
        __syncwarp();
        prefix |= found[w][0] << shift;
        needed -= (int)found[w][1];
        __syncwarp();
    }

    // emit strictly-greater, then `needed` ties at threshold (lowest idx first)
    if (lane == 0) tie_cnt[w] = 0;
    __syncwarp();
#pragma unroll
    for (int j = 0; j < 32; j++) {
        if (keys[j] > prefix) orow[j * 32 + lane] = vals[j];
        else if (keys[j] == prefix) {
            unsigned p = atomicAdd(&tie_cnt[w], 1u);
            if (p < 64) tie_idx[w][p] = (unsigned)(j * 32 + lane);
        }
    }
    __syncwarp();
    if (lane == 0) {
        int cnt = tie_cnt[w] < 64 ? (int)tie_cnt[w] : 64;
        unsigned ku = (prefix & 0x80000000u) ? (prefix ^ 0x80000000u) : ~prefix;
        float kval = __uint_as_float(ku);
        for (int e = 0; e < needed; e++) {
            int bi = -1; unsigned bidx = 0xFFFFFFFFu;
            for (int t = 0; t < cnt; t++)
                if (tie_idx[w][t] < bidx) { bidx = tie_idx[w][t]; bi = t; }
            if (bi >= 0) { orow[bidx] = kval; tie_idx[w][bi] = 0xFFFFFFFFu; }
        }
    }
}

// ---------------------------------------------------------------------------
extern "C" void kernel_launch(void* const* d_in, const int* in_sizes, int n_in,
                              void* d_out, int out_size)
{
    const float* x     = (const float*)d_in[0];
    const float* Wq    = (const float*)d_in[1];
    const float* bq    = (const float*)d_in[2];
    const float* Wk    = (const float*)d_in[3];
    const float* bk    = (const float*)d_in[4];
    const float* mlp_w = (const float*)d_in[5];
    const float* mlp_b = (const float*)d_in[6];

    float* out = (float*)d_out;

    qk_kernel<<<768, 128>>>(x, Wq, bq, Wk, bk);

    cudaFuncSetAttribute(score_kernel,
                         cudaFuncAttributeMaxDynamicSharedMemorySize, SMEMSZ);
    score_kernel<<<BATCH * (NODES / 128), 256, SMEMSZ>>>(mlp_w, mlp_b);

    topk_kernel<<<BATCH * NODES / 8, 256>>>(out);
}